// round 11
// baseline (speedup 1.0000x reference)
#include <cuda_runtime.h>

#define NC      6
#define NWARPS  8
#define TPB     256
#define NBLOCKS 444    // 148 SMs * 3 (3 CTAs/SM -> 85 regs/thread budget)
#define NVALS   13     // ht[6], hp[6], dsum

// Per-block partials, [val][block]; fully overwritten each launch.
__device__ unsigned int g_part[NVALS][NBLOCKS];
__device__ unsigned int g_ticket;   // last-block-done counter; reset by last block

__device__ __forceinline__ void process_group(
    float4 f0, float4 f1, float4 f2, int2 t2,
    unsigned long long& ht_pack, unsigned long long& hp_pack, unsigned int& dsum)
{
    float v[12];
    v[0]=f0.x; v[1]=f0.y; v[2]=f0.z;  v[3]=f0.w;
    v[4]=f1.x; v[5]=f1.y; v[6]=f1.z;  v[7]=f1.w;
    v[8]=f2.x; v[9]=f2.y; v[10]=f2.z; v[11]=f2.w;

    int tt[2];
    tt[0] = t2.x; tt[1] = t2.y;

    #pragma unroll
    for (int r = 0; r < 2; r++) {
        const int base = r * 6;
        float bv = v[base];
        int   bi = 0;
        #pragma unroll
        for (int c = 1; c < 6; c++) {
            // strict > keeps FIRST max, matching jnp.argmax tie-break
            if (v[base + c] > bv) { bv = v[base + c]; bi = c; }
        }
        const int t = tt[r];
        const int d = t - bi;
        dsum    += (unsigned)(d * d);
        ht_pack += 1ull << (t  * 10);
        hp_pack += 1ull << (bi * 10);
    }
}

__global__ void __launch_bounds__(TPB, 3) kappa_fused_kernel(
    const float* __restrict__ yp,
    const int* __restrict__ yt,     // y_true is int32 (JAX x64-demotion)
    int n,
    float* __restrict__ out)
{
    const int tid  = threadIdx.x;
    const int warp = tid >> 5;
    const int lane = tid & 31;

    // Register accumulators: packed 6x10-bit histograms + squared-diff sum.
    unsigned long long ht_pack = 0ull;
    unsigned long long hp_pack = 0ull;
    unsigned int dsum = 0u;

    const int ngroups = n >> 1;                   // groups of 2 rows
    const float4* yp4 = (const float4*)yp;        // 3 float4 per group (12 floats)
    const int2*   yt2 = (const int2*)yt;          // 1 int2 per group (2 labels)
    const int stride = gridDim.x * blockDim.x;

    // Depth-2 software pipeline: TWO groups' loads in flight at all times
    // (slots a/b alternate; each refills itself at distance 2*stride).
    // In-flight bytes/thread = 112 -> 3.5KB/warp -> ~86KB/SM @ 24 warps.
    const int g0 = blockIdx.x * blockDim.x + tid;

    float4 a0, a1, a2; int2 at;
    float4 b0, b1, b2; int2 bt;
    bool ha = (g0 < ngroups);
    bool hb = (g0 + stride < ngroups);
    if (ha) {
        a0 = __ldcg(&yp4[(size_t)g0 * 3 + 0]);
        a1 = __ldcg(&yp4[(size_t)g0 * 3 + 1]);
        a2 = __ldcg(&yp4[(size_t)g0 * 3 + 2]);
        at = __ldcg(&yt2[g0]);
    }
    if (hb) {
        const int g1 = g0 + stride;
        b0 = __ldcg(&yp4[(size_t)g1 * 3 + 0]);
        b1 = __ldcg(&yp4[(size_t)g1 * 3 + 1]);
        b2 = __ldcg(&yp4[(size_t)g1 * 3 + 2]);
        bt = __ldcg(&yt2[g1]);
    }
    int gn = g0 + 2 * stride;   // next group index to fetch

    while (true) {
        if (!ha) break;
        process_group(a0, a1, a2, at, ht_pack, hp_pack, dsum);
        ha = (gn < ngroups);
        if (ha) {
            a0 = __ldcg(&yp4[(size_t)gn * 3 + 0]);
            a1 = __ldcg(&yp4[(size_t)gn * 3 + 1]);
            a2 = __ldcg(&yp4[(size_t)gn * 3 + 2]);
            at = __ldcg(&yt2[gn]);
        }
        gn += stride;

        if (!hb) break;
        process_group(b0, b1, b2, bt, ht_pack, hp_pack, dsum);
        hb = (gn < ngroups);
        if (hb) {
            b0 = __ldcg(&yp4[(size_t)gn * 3 + 0]);
            b1 = __ldcg(&yp4[(size_t)gn * 3 + 1]);
            b2 = __ldcg(&yp4[(size_t)gn * 3 + 2]);
            bt = __ldcg(&yt2[gn]);
        }
        gn += stride;
    }

    // Tail row (n odd): block 0, thread 0.
    if (blockIdx.x == 0 && tid == 0 && (n & 1)) {
        const int r = n - 1;
        const float* row = yp + (size_t)r * 6;
        float bv = row[0];
        int   bi = 0;
        #pragma unroll
        for (int c = 1; c < 6; c++) {
            float x = row[c];
            if (x > bv) { bv = x; bi = c; }
        }
        const int t = yt[r];
        const int d = t - bi;
        dsum    += (unsigned)(d * d);
        ht_pack += 1ull << (t  * 10);
        hp_pack += 1ull << (bi * 10);
    }

    // Unpack to 13 u32 and warp shuffle-reduce.
    unsigned int vals[NVALS];
    #pragma unroll
    for (int c = 0; c < NC; c++) {
        vals[c]      = (unsigned int)((ht_pack >> (c * 10)) & 0x3FFu);
        vals[NC + c] = (unsigned int)((hp_pack >> (c * 10)) & 0x3FFu);
    }
    vals[12] = dsum;

    #pragma unroll
    for (int k = 0; k < NVALS; k++) {
        unsigned int s = vals[k];
        #pragma unroll
        for (int o = 16; o; o >>= 1)
            s += __shfl_xor_sync(0xffffffffu, s, o);
        vals[k] = s;
    }

    // Block merge via shared: lane 0 of each warp deposits its 13 sums.
    __shared__ unsigned int s_w[NWARPS][NVALS];
    if (lane == 0) {
        #pragma unroll
        for (int k = 0; k < NVALS; k++) s_w[warp][k] = vals[k];
    }
    __syncthreads();
    if (tid < NVALS) {
        unsigned int s = 0;
        #pragma unroll
        for (int w = 0; w < NWARPS; w++) s += s_w[w][tid];
        g_part[tid][blockIdx.x] = s;
    }
    __threadfence();   // release partials
    __syncthreads();

    // Last-block-done: final reduce + kappa.
    __shared__ unsigned int s_last;
    __shared__ unsigned int s_acc[NVALS];
    if (tid == 0)
        s_last = (atomicAdd(&g_ticket, 1u) == (unsigned)(gridDim.x - 1)) ? 1u : 0u;
    __syncthreads();
    if (!s_last) return;

    __threadfence();   // acquire: all blocks' partials visible

    if (tid < NVALS) s_acc[tid] = 0u;
    __syncthreads();

    // 13 values x 19 slices = 247 active threads.
    {
        const int k     = tid % NVALS;
        const int slice = tid / NVALS;
        if (slice < 19) {
            volatile const unsigned int* row = &g_part[k][0];
            unsigned int s = 0;
            for (int b = slice; b < NBLOCKS; b += 19) s += row[b];
            atomicAdd(&s_acc[k], s);
        }
    }
    __syncthreads();

    if (tid == 0) {
        double ht[NC], hp[NC];
        #pragma unroll
        for (int c = 0; c < NC; c++) {
            ht[c] = (double)s_acc[c];
            hp[c] = (double)s_acc[NC + c];
        }
        const double num = (double)s_acc[12];   // sum W*conf (unnormalized)
        double den = 0.0;
        #pragma unroll
        for (int i = 0; i < NC; i++)
            #pragma unroll
            for (int j = 0; j < NC; j++)
                den += (double)((i - j) * (i - j)) * ht[i] * hp[j];
        const double N = (double)n;
        out[0] = (float)(1.0 - (num * N) / den);
        g_ticket = 0u;   // reset for next graph replay (deterministic)
    }
}

extern "C" void kernel_launch(void* const* d_in, const int* in_sizes, int n_in,
                              void* d_out, int out_size) {
    const float* yp  = (const float*)d_in[0];
    const int*   yt  = (const int*)d_in[1];
    float*       out = (float*)d_out;
    const int n = in_sizes[1];   // number of rows (y_true element count)

    kappa_fused_kernel<<<NBLOCKS, TPB>>>(yp, yt, n, out);
}